// round 6
// baseline (speedup 1.0000x reference)
#include <cuda_runtime.h>
#include <cuda_bf16.h>
#include <cstdint>

#define V      12288
#define E      128
#define NTI    96
#define SSTR   136                 // bf16 tile row stride (128 + 8 pad)
#define BSTR   68                  // acc buffer row stride in floats (64 + 4 pad)
#define AB_BYTES   (2 * 128 * SSTR * 2)          // 69632 (A + B)
#define BUF_BYTES  (128 * BSTR * 4)              // 34816
#define SMEM_BYTES (AB_BYTES + BUF_BYTES)        // 104448

// ---------------------------------------------------------------------------
__device__ __nv_bfloat16 g_ctx[V * E];
__device__ __nv_bfloat16 g_tgt[V * E];

__global__ void convert_kernel(const float* __restrict__ tgt,
                               const float* __restrict__ ctx,
                               float* __restrict__ out) {
    if (blockIdx.x == 0 && threadIdx.x == 0) out[0] = 0.0f;
    int t = blockIdx.x * blockDim.x + threadIdx.x;
    int base = t * 8;
    if (base >= V * E) return;
    float4 a0 = *(const float4*)(tgt + base);
    float4 a1 = *(const float4*)(tgt + base + 4);
    float4 b0 = *(const float4*)(ctx + base);
    float4 b1 = *(const float4*)(ctx + base + 4);
    __nv_bfloat162 ta[4], ca[4];
    ta[0] = __floats2bfloat162_rn(a0.x, a0.y); ta[1] = __floats2bfloat162_rn(a0.z, a0.w);
    ta[2] = __floats2bfloat162_rn(a1.x, a1.y); ta[3] = __floats2bfloat162_rn(a1.z, a1.w);
    ca[0] = __floats2bfloat162_rn(b0.x, b0.y); ca[1] = __floats2bfloat162_rn(b0.z, b0.w);
    ca[2] = __floats2bfloat162_rn(b1.x, b1.y); ca[3] = __floats2bfloat162_rn(b1.z, b1.w);
    *(uint4*)(g_tgt + base) = *(const uint4*)ta;
    *(uint4*)(g_ctx + base) = *(const uint4*)ca;
}

// ---------------------------------------------------------------------------
__device__ __forceinline__ uint32_t smem_u32(const void* p) {
    uint32_t a;
    asm("{ .reg .u64 t; cvta.to.shared.u64 t, %1; cvt.u32.u64 %0, t; }" : "=r"(a) : "l"(p));
    return a;
}
__device__ __forceinline__ void mma_bf16(float c[4], const uint32_t a[4],
                                         const uint32_t b[2]) {
    asm volatile(
        "mma.sync.aligned.m16n8k16.row.col.f32.bf16.bf16.f32 "
        "{%0,%1,%2,%3}, {%4,%5,%6,%7}, {%8,%9}, {%0,%1,%2,%3};\n"
        : "+f"(c[0]), "+f"(c[1]), "+f"(c[2]), "+f"(c[3])
        : "r"(a[0]), "r"(a[1]), "r"(a[2]), "r"(a[3]), "r"(b[0]), "r"(b[1]));
}
__device__ __forceinline__ void ldsm_x4(uint32_t r[4], uint32_t addr) {
    asm volatile("ldmatrix.sync.aligned.m8n8.x4.shared.b16 {%0,%1,%2,%3}, [%4];"
                 : "=r"(r[0]), "=r"(r[1]), "=r"(r[2]), "=r"(r[3]) : "r"(addr));
}
__device__ __forceinline__ float lg2f(float v) {
    float r; asm("lg2.approx.f32 %0, %1;" : "=f"(r) : "f"(v)); return r;
}
__device__ __forceinline__ float ex2f(float v) {
    float r; asm("ex2.approx.f32 %0, %1;" : "=f"(r) : "f"(v)); return r;
}
__device__ __forceinline__ float4 ldcs4(const float* p) {
    float4 v;
    asm volatile("ld.global.cs.v4.f32 {%0,%1,%2,%3}, [%4];"
                 : "=f"(v.x), "=f"(v.y), "=f"(v.z), "=f"(v.w) : "l"(p));
    return v;
}

// ---------------------------------------------------------------------------
// GEMM pass: warp tile 32(M) x 32(N), K=128 in 8 steps. acc via mma.sync.
// ---------------------------------------------------------------------------
__device__ __forceinline__ void gemm_pass(uint32_t aAddr0, uint32_t aAddr1,
                                          uint32_t bAddr0, uint32_t bAddr1,
                                          float acc[2][4][4]) {
    #pragma unroll
    for (int mt = 0; mt < 2; mt++)
        #pragma unroll
        for (int nt = 0; nt < 4; nt++)
            #pragma unroll
            for (int r = 0; r < 4; r++) acc[mt][nt][r] = 0.0f;

    #pragma unroll
    for (int ks = 0; ks < 8; ks++) {
        const uint32_t koff = ks * 32;           // 16 bf16 = 32 bytes
        uint32_t afr[2][4], b01[4], b23[4];
        ldsm_x4(afr[0], aAddr0 + koff);
        ldsm_x4(afr[1], aAddr1 + koff);
        ldsm_x4(b01,    bAddr0 + koff);
        ldsm_x4(b23,    bAddr1 + koff);
        #pragma unroll
        for (int mt = 0; mt < 2; mt++) {
            mma_bf16(acc[mt][0], afr[mt], &b01[0]);
            mma_bf16(acc[mt][1], afr[mt], &b01[2]);
            mma_bf16(acc[mt][2], afr[mt], &b23[0]);
            mma_bf16(acc[mt][3], afr[mt], &b23[2]);
        }
    }
}

// Store one pass's acc (32x32 per warp) into buf[128][BSTR].
__device__ __forceinline__ void sts_acc(float* __restrict__ buf, const float acc[2][4][4],
                                        int m0, int wn, int g, int tig) {
    #pragma unroll
    for (int mt = 0; mt < 2; mt++)
        #pragma unroll
        for (int h = 0; h < 2; h++) {
            const int row = m0 + 16 * mt + 8 * h + g;
            float* bp = buf + row * BSTR + wn * 32 + 2 * tig;
            #pragma unroll
            for (int nt = 0; nt < 4; nt++)
                *(float2*)(bp + 8 * nt) = make_float2(acc[mt][nt][2 * h],
                                                      acc[mt][nt][2 * h + 1]);
        }
}

// Epilogue: warp covers rows warp*16..+15, 64 cols (2 strips) of this pass.
// X loads fully coalesced float4; one-iteration prefetch.
__device__ __forceinline__ void epi_pass(const float* __restrict__ X,
                                         const float* __restrict__ tb,
                                         const float* __restrict__ cb,
                                         const float* __restrict__ buf,
                                         int bi, int bj, int pass,
                                         int warp, int lane, float& lsum) {
    const int sub   = lane >> 4;            // row parity within pair
    const int l16   = lane & 15;
    const int strip = l16 >> 3;             // 0..1 -> col strips 0 / 64
    const int c4    = (l16 & 7) << 2;       // 0,4,...,28
    const int jg    = bj * 128 + strip * 64 + pass * 32 + c4;
    const int bcol  = strip * 32 + c4;

    const float4 tb4 = *(const float4*)(tb + jg);

    int rl = warp * 16 + sub;
    float4 xv = ldcs4(X + (size_t)(bi * 128 + rl) * V + jg);

    #pragma unroll
    for (int rr = 0; rr < 8; rr++) {
        const int rln = rl + 2;
        float4 xn;
        if (rr < 7) xn = ldcs4(X + (size_t)(bi * 128 + rln) * V + jg);
        const float cbv = __ldg(cb + bi * 128 + rl);
        const float4 av = *(const float4*)(buf + rl * BSTR + bcol);

        float d, w;
        d = fmaf(-0.69314718f, lg2f(1.0f + xv.x), av.x + tb4.x + cbv);
        w = fminf(ex2f(fmaf(0.75f, lg2f(xv.x), -4.98289214f)), 1.0f);
        lsum = fmaf(w * d, d, lsum);
        d = fmaf(-0.69314718f, lg2f(1.0f + xv.y), av.y + tb4.y + cbv);
        w = fminf(ex2f(fmaf(0.75f, lg2f(xv.y), -4.98289214f)), 1.0f);
        lsum = fmaf(w * d, d, lsum);
        d = fmaf(-0.69314718f, lg2f(1.0f + xv.z), av.z + tb4.z + cbv);
        w = fminf(ex2f(fmaf(0.75f, lg2f(xv.z), -4.98289214f)), 1.0f);
        lsum = fmaf(w * d, d, lsum);
        d = fmaf(-0.69314718f, lg2f(1.0f + xv.w), av.w + tb4.w + cbv);
        w = fminf(ex2f(fmaf(0.75f, lg2f(xv.w), -4.98289214f)), 1.0f);
        lsum = fmaf(w * d, d, lsum);

        xv = xn;
        rl = rln;
    }
}

// ---------------------------------------------------------------------------
// One 128x128 tile per block. 8 warps: GEMM as 4Mx2N (warp 32x64, two 32-col
// passes); epilogue re-partitioned as 16 rows/warp, fully coalesced X.
// ---------------------------------------------------------------------------
__global__ void __launch_bounds__(256, 2)
glove_mma(const float* __restrict__ X,
          const float* __restrict__ tb,
          const float* __restrict__ cb,
          float* __restrict__ out) {
    extern __shared__ char smem[];
    __nv_bfloat16* As = (__nv_bfloat16*)smem;
    __nv_bfloat16* Bs = (__nv_bfloat16*)(smem + 128 * SSTR * 2);
    float* buf0 = (float*)(smem + AB_BYTES);    // pass-0 acc
    float* buf1 = (float*)smem;                 // pass-1 acc, overlays As/Bs
    __shared__ float red[8];

    const int bi = blockIdx.y, bj = blockIdx.x;
    const int tid  = threadIdx.x;
    const int warp = tid >> 5;
    const int lane = tid & 31;
    const int wm   = warp >> 1;
    const int wn   = warp & 1;
    const int g    = lane >> 2;
    const int tig  = lane & 3;
    const int m0   = wm * 32;
    const int n0   = wn * 64;

    // ---- stage A (ctx) and B (tgt), K=128 ------------------------------------
    {
        const __nv_bfloat16* gA = g_ctx + (size_t)(bi * 128) * E;
        const __nv_bfloat16* gB = g_tgt + (size_t)(bj * 128) * E;
        #pragma unroll
        for (int u = tid; u < 128 * 16; u += 256) {
            int row = u >> 4, part = u & 15;
            *(uint4*)(As + row * SSTR + part * 8) = *(const uint4*)(gA + row * E + part * 8);
            *(uint4*)(Bs + row * SSTR + part * 8) = *(const uint4*)(gB + row * E + part * 8);
        }
    }
    __syncthreads();

    // ---- LDSM base addresses --------------------------------------------------
    const int arow = (lane & 15);
    const int acol = (lane >> 4) << 3;
    const uint32_t aAddr0 = smem_u32(As + (m0 + arow) * SSTR + acol);
    const uint32_t aAddr1 = aAddr0 + 16 * SSTR * 2;
    const int bstrip = (lane >> 4);
    const int bkh    = ((lane >> 3) & 1) << 3;
    const int brow   = (lane & 7);
    const uint32_t bAddr0 = smem_u32(Bs + (n0 + (0 + bstrip) * 8 + brow) * SSTR + bkh);
    const uint32_t bAddr1 = smem_u32(Bs + (n0 + (2 + bstrip) * 8 + brow) * SSTR + bkh);
    const uint32_t poff = (uint32_t)(32 * SSTR * 2);

    float lsum = 0.0f;
    float acc[2][4][4];

    // pass 0 GEMM -> buf0, pass 1 GEMM (As/Bs still intact)
    gemm_pass(aAddr0, aAddr1, bAddr0, bAddr1, acc);
    sts_acc(buf0, acc, m0, wn, g, tig);
    gemm_pass(aAddr0, aAddr1, bAddr0 + poff, bAddr1 + poff, acc);
    __syncthreads();                       // GEMM reads done; buf0 complete

    sts_acc(buf1, acc, m0, wn, g, tig);    // overlay As/Bs
    epi_pass(X, tb, cb, buf0, bi, bj, 0, warp, lane, lsum);
    __syncthreads();                       // buf1 complete

    epi_pass(X, tb, cb, buf1, bi, bj, 1, warp, lane, lsum);

    // ---- reduce + one atomic per block -----------------------------------------
    #pragma unroll
    for (int off = 16; off; off >>= 1) lsum += __shfl_xor_sync(0xFFFFFFFFu, lsum, off);
    if (lane == 0) red[warp] = lsum;
    __syncthreads();
    if (tid == 0) {
        float s = 0.0f;
        #pragma unroll
        for (int w = 0; w < 8; ++w) s += red[w];
        atomicAdd(out, s);
    }
}

// ---------------------------------------------------------------------------
extern "C" void kernel_launch(void* const* d_in, const int* in_sizes, int n_in,
                              void* d_out, int out_size) {
    const float* X   = (const float*)d_in[0];
    const float* te  = (const float*)d_in[1];
    const float* ce  = (const float*)d_in[2];
    const float* tbp = (const float*)d_in[3];
    const float* cbp = (const float*)d_in[4];
    float* out = (float*)d_out;

    static bool attr_set = false;
    if (!attr_set) {
        cudaFuncSetAttribute(glove_mma, cudaFuncAttributeMaxDynamicSharedMemorySize,
                             SMEM_BYTES);
        attr_set = true;
    }

    const int conv_threads = V * E / 8;
    convert_kernel<<<(conv_threads + 255) / 256, 256>>>(te, ce, out);

    dim3 grid(NTI, NTI);
    glove_mma<<<grid, 256, SMEM_BYTES>>>(X, tbp, cbp, out);
    (void)in_sizes; (void)n_in; (void)out_size;
}

// round 7
// speedup vs baseline: 1.1917x; 1.1917x over previous
#include <cuda_runtime.h>
#include <cuda_bf16.h>
#include <cstdint>

#define V      12288
#define E      128
#define NTI    96
#define SSTR   136                 // bf16 tile row stride (128 + 8 pad)
#define BSTR   136                 // acc buffer row stride in floats
#define SMEM_BYTES (2 * 128 * SSTR * 2)   // 69632; acc buf (128*136*4) overlays exactly

// ---------------------------------------------------------------------------
__device__ __nv_bfloat16 g_ctx[V * E];
__device__ __nv_bfloat16 g_tgt[V * E];

__global__ void convert_kernel(const float* __restrict__ tgt,
                               const float* __restrict__ ctx,
                               float* __restrict__ out) {
    if (blockIdx.x == 0 && threadIdx.x == 0) out[0] = 0.0f;
    int t = blockIdx.x * blockDim.x + threadIdx.x;
    int base = t * 8;
    if (base >= V * E) return;
    float4 a0 = *(const float4*)(tgt + base);
    float4 a1 = *(const float4*)(tgt + base + 4);
    float4 b0 = *(const float4*)(ctx + base);
    float4 b1 = *(const float4*)(ctx + base + 4);
    __nv_bfloat162 ta[4], ca[4];
    ta[0] = __floats2bfloat162_rn(a0.x, a0.y); ta[1] = __floats2bfloat162_rn(a0.z, a0.w);
    ta[2] = __floats2bfloat162_rn(a1.x, a1.y); ta[3] = __floats2bfloat162_rn(a1.z, a1.w);
    ca[0] = __floats2bfloat162_rn(b0.x, b0.y); ca[1] = __floats2bfloat162_rn(b0.z, b0.w);
    ca[2] = __floats2bfloat162_rn(b1.x, b1.y); ca[3] = __floats2bfloat162_rn(b1.z, b1.w);
    *(uint4*)(g_tgt + base) = *(const uint4*)ta;
    *(uint4*)(g_ctx + base) = *(const uint4*)ca;
}

// ---------------------------------------------------------------------------
__device__ __forceinline__ uint32_t smem_u32(const void* p) {
    uint32_t a;
    asm("{ .reg .u64 t; cvta.to.shared.u64 t, %1; cvt.u32.u64 %0, t; }" : "=r"(a) : "l"(p));
    return a;
}
__device__ __forceinline__ void mma_bf16(float c[4], const uint32_t a[4],
                                         const uint32_t b[2]) {
    asm volatile(
        "mma.sync.aligned.m16n8k16.row.col.f32.bf16.bf16.f32 "
        "{%0,%1,%2,%3}, {%4,%5,%6,%7}, {%8,%9}, {%0,%1,%2,%3};\n"
        : "+f"(c[0]), "+f"(c[1]), "+f"(c[2]), "+f"(c[3])
        : "r"(a[0]), "r"(a[1]), "r"(a[2]), "r"(a[3]), "r"(b[0]), "r"(b[1]));
}
__device__ __forceinline__ void ldsm_x4(uint32_t r[4], uint32_t addr) {
    asm volatile("ldmatrix.sync.aligned.m8n8.x4.shared.b16 {%0,%1,%2,%3}, [%4];"
                 : "=r"(r[0]), "=r"(r[1]), "=r"(r[2]), "=r"(r[3]) : "r"(addr));
}
__device__ __forceinline__ float lg2f(float v) {
    float r; asm("lg2.approx.f32 %0, %1;" : "=f"(r) : "f"(v)); return r;
}
__device__ __forceinline__ float ex2f(float v) {
    float r; asm("ex2.approx.f32 %0, %1;" : "=f"(r) : "f"(v)); return r;
}
__device__ __forceinline__ float4 ldcs4(const float* p) {
    float4 v;
    asm volatile("ld.global.cs.v4.f32 {%0,%1,%2,%3}, [%4];"
                 : "=f"(v.x), "=f"(v.y), "=f"(v.z), "=f"(v.w) : "l"(p));
    return v;
}

// Process 4 elements of one float4 against acc+biases base.
__device__ __forceinline__ void epi4(const float4 xv, const float4 av,
                                     const float4 tb4, const float cbv,
                                     float& lsum) {
    float d, w;
    d = fmaf(-0.69314718f, lg2f(1.0f + xv.x), av.x + tb4.x + cbv);
    w = fminf(ex2f(fmaf(0.75f, lg2f(xv.x), -4.98289214f)), 1.0f);
    lsum = fmaf(w * d, d, lsum);
    d = fmaf(-0.69314718f, lg2f(1.0f + xv.y), av.y + tb4.y + cbv);
    w = fminf(ex2f(fmaf(0.75f, lg2f(xv.y), -4.98289214f)), 1.0f);
    lsum = fmaf(w * d, d, lsum);
    d = fmaf(-0.69314718f, lg2f(1.0f + xv.z), av.z + tb4.z + cbv);
    w = fminf(ex2f(fmaf(0.75f, lg2f(xv.z), -4.98289214f)), 1.0f);
    lsum = fmaf(w * d, d, lsum);
    d = fmaf(-0.69314718f, lg2f(1.0f + xv.w), av.w + tb4.w + cbv);
    w = fminf(ex2f(fmaf(0.75f, lg2f(xv.w), -4.98289214f)), 1.0f);
    lsum = fmaf(w * d, d, lsum);
}

// ---------------------------------------------------------------------------
// One 128x128 tile per block. 256 threads = 8 warps.
// GEMM: 4M x 2N warps, warp tile 32x64 in ONE pass (acc 64 regs, A read once).
// Acc -> smem remap; epilogue: warp = 16 rows x 128 cols, X coalesced float4.
// ---------------------------------------------------------------------------
__global__ void __launch_bounds__(256, 2)
glove_mma(const float* __restrict__ X,
          const float* __restrict__ tb,
          const float* __restrict__ cb,
          float* __restrict__ out) {
    extern __shared__ char smem[];
    __nv_bfloat16* As = (__nv_bfloat16*)smem;
    __nv_bfloat16* Bs = (__nv_bfloat16*)(smem + 128 * SSTR * 2);
    float* buf = (float*)smem;                 // overlays As/Bs after GEMM
    __shared__ float red[8];

    const int bi = blockIdx.y, bj = blockIdx.x;
    const int tid  = threadIdx.x;
    const int warp = tid >> 5;
    const int lane = tid & 31;
    const int wm   = warp >> 1;
    const int wn   = warp & 1;
    const int g    = lane >> 2;
    const int tig  = lane & 3;
    const int m0   = wm * 32;
    const int n0   = wn * 64;

    // ---- stage A (ctx) and B (tgt), K=128 ------------------------------------
    {
        const __nv_bfloat16* gA = g_ctx + (size_t)(bi * 128) * E;
        const __nv_bfloat16* gB = g_tgt + (size_t)(bj * 128) * E;
        #pragma unroll
        for (int u = tid; u < 128 * 16; u += 256) {
            int row = u >> 4, part = u & 15;
            *(uint4*)(As + row * SSTR + part * 8) = *(const uint4*)(gA + row * E + part * 8);
            *(uint4*)(Bs + row * SSTR + part * 8) = *(const uint4*)(gB + row * E + part * 8);
        }
    }

    // Epilogue-layout X mapping (independent of GEMM layout).
    const int sub  = lane >> 4;          // row parity
    const int l16  = lane & 15;          // 16 lanes x float4 = 64 cols
    const int rbas = warp * 16 + sub;    // local row base (rows rbas + 2k)
    const float* xbase = X + (size_t)(bi * 128 + rbas) * V + bj * 128 + 4 * l16;

    float4 xq[4];
    // Prefetch X for idx 0,1 (row rbas, both col halves) — GEMM hides latency.
    xq[0] = ldcs4(xbase);
    xq[1] = ldcs4(xbase + 64);

    __syncthreads();

    // ---- LDSM base addresses --------------------------------------------------
    const int arow = (lane & 15);
    const int acol = (lane >> 4) << 3;
    const uint32_t aAddr0 = smem_u32(As + (m0 + arow) * SSTR + acol);
    const uint32_t aAddr1 = aAddr0 + 16 * SSTR * 2;
    const int bstrip = (lane >> 4);
    const int bkh    = ((lane >> 3) & 1) << 3;
    const int brow   = (lane & 7);
    uint32_t bAddr[4];
    #pragma unroll
    for (int q = 0; q < 4; q++)
        bAddr[q] = smem_u32(Bs + (n0 + (2 * q + bstrip) * 8 + brow) * SSTR + bkh);

    // ---- single-pass GEMM: 32x64 per warp, K=128 -------------------------------
    float acc[2][8][4];
    #pragma unroll
    for (int mt = 0; mt < 2; mt++)
        #pragma unroll
        for (int nt = 0; nt < 8; nt++)
            #pragma unroll
            for (int r = 0; r < 4; r++) acc[mt][nt][r] = 0.0f;

    #pragma unroll
    for (int ks = 0; ks < 8; ks++) {
        const uint32_t koff = ks * 32;
        uint32_t afr[2][4], bfr[4][4];
        ldsm_x4(afr[0], aAddr0 + koff);
        ldsm_x4(afr[1], aAddr1 + koff);
        #pragma unroll
        for (int q = 0; q < 4; q++) ldsm_x4(bfr[q], bAddr[q] + koff);
        #pragma unroll
        for (int mt = 0; mt < 2; mt++)
            #pragma unroll
            for (int q = 0; q < 4; q++) {
                mma_bf16(acc[mt][2 * q],     afr[mt], &bfr[q][0]);
                mma_bf16(acc[mt][2 * q + 1], afr[mt], &bfr[q][2]);
            }
    }

    // Prefetch X for idx 2,3 (row rbas+2) while waiting at the sync.
    xq[2] = ldcs4(xbase + 2 * V);
    xq[3] = ldcs4(xbase + 2 * V + 64);

    __syncthreads();                 // all warps done reading As/Bs

    // ---- remap acc -> buf (overlay) --------------------------------------------
    #pragma unroll
    for (int mt = 0; mt < 2; mt++)
        #pragma unroll
        for (int h = 0; h < 2; h++) {
            const int row = m0 + 16 * mt + 8 * h + g;
            float* bp = buf + row * BSTR + n0 + 2 * tig;
            #pragma unroll
            for (int nt = 0; nt < 8; nt++)
                *(float2*)(bp + 8 * nt) = make_float2(acc[mt][nt][2 * h],
                                                      acc[mt][nt][2 * h + 1]);
        }
    __syncthreads();                 // buf complete

    // ---- epilogue: 16 rows x 128 cols per warp, X coalesced --------------------
    const float4 tb4a = *(const float4*)(tb + bj * 128 + 4 * l16);
    const float4 tb4b = *(const float4*)(tb + bj * 128 + 64 + 4 * l16);
    float lsum = 0.0f;

    #pragma unroll
    for (int idx = 0; idx < 16; idx++) {
        const int k    = idx >> 1;
        const int half = idx & 1;
        const int rl   = rbas + 2 * k;
        float4 xv = xq[idx & 3];
        if (idx + 4 < 16) {
            const int ni = idx + 4;
            xq[idx & 3] = ldcs4(xbase + (size_t)(2 * (ni >> 1)) * V + 64 * (ni & 1));
        }
        const float cbv = __ldg(cb + bi * 128 + rl);
        const float4 av = *(const float4*)(buf + rl * BSTR + 64 * half + 4 * l16);
        epi4(xv, av, half ? tb4b : tb4a, cbv, lsum);
    }

    // ---- reduce + one atomic per block ------------------------------------------
    #pragma unroll
    for (int off = 16; off; off >>= 1) lsum += __shfl_xor_sync(0xFFFFFFFFu, lsum, off);
    if (lane == 0) red[warp] = lsum;
    __syncthreads();
    if (tid == 0) {
        float s = 0.0f;
        #pragma unroll
        for (int w = 0; w < 8; ++w) s += red[w];
        atomicAdd(out, s);
    }
}

// ---------------------------------------------------------------------------
extern "C" void kernel_launch(void* const* d_in, const int* in_sizes, int n_in,
                              void* d_out, int out_size) {
    const float* X   = (const float*)d_in[0];
    const float* te  = (const float*)d_in[1];
    const float* ce  = (const float*)d_in[2];
    const float* tbp = (const float*)d_in[3];
    const float* cbp = (const float*)d_in[4];
    float* out = (float*)d_out;

    static bool attr_set = false;
    if (!attr_set) {
        cudaFuncSetAttribute(glove_mma, cudaFuncAttributeMaxDynamicSharedMemorySize,
                             SMEM_BYTES);
        attr_set = true;
    }

    const int conv_threads = V * E / 8;
    convert_kernel<<<(conv_threads + 255) / 256, 256>>>(te, ce, out);

    dim3 grid(NTI, NTI);
    glove_mma<<<grid, 256, SMEM_BYTES>>>(X, tbp, cbp, out);
    (void)in_sizes; (void)n_in; (void)out_size;
}